// round 1
// baseline (speedup 1.0000x reference)
#include <cuda_runtime.h>
#include <math.h>

#define B_    64
#define I_    48
#define O_    48
#define F_    256
#define H_    256
#define FIVEH 1280

// ---------------- scratch (device globals; no allocations allowed) ----------
__device__ float g_PX[I_ * B_ * FIVEH];      // x @ Wx[:F]      per (i,b,col)
__device__ float g_PY[O_ * B_ * FIVEH];      // y @ Wx[F:2F]    per (j,b,col)
__device__ float g_S[2][I_ * B_ * H_];       // double-buffered s state
__device__ float g_C[2][I_ * B_ * H_];       // double-buffered c state

__device__ __forceinline__ float sigf(float x) { return 1.0f / (1.0f + expf(-x)); }

// ---------------------------------------------------------------------------
// Precompute kernel: P[cell][b][col] = sum_k A[b][cell][k] * Wx[k + koff][col]
// which = blockIdx.z: 0 -> x / Wx rows [0,256)  -> g_PX
//                     1 -> y / Wx rows [256,512)-> g_PY
// Tile: BM=64 (all batches), BN=128, BK=16. 256 threads, thread tile 4x8.
// ---------------------------------------------------------------------------
__global__ __launch_bounds__(256) void precompute_kernel(
    const float* __restrict__ x, const float* __restrict__ y,
    const float* __restrict__ Wx)
{
    const int cell  = blockIdx.x;          // i (or j)
    const int n0    = blockIdx.y * 128;    // column tile
    const int which = blockIdx.z;

    const float* A    = which ? y : x;
    const int    koff = which ? F_ : 0;
    float*       P    = which ? g_PY : g_PX;

    __shared__ float As[16][68];
    __shared__ float Bs[16][128];

    const int t  = threadIdx.x;
    const int tx = t & 15, ty = t >> 4;
    const int lm = t >> 2, lk = (t & 3) * 4;

    float acc[4][8];
#pragma unroll
    for (int r = 0; r < 4; r++)
#pragma unroll
        for (int q = 0; q < 8; q++) acc[r][q] = 0.f;

    for (int k0 = 0; k0 < F_; k0 += 16) {
        // A: [64 x 16] tile, one float4 per thread, stored transposed
        float4 av = *(const float4*)&A[(lm * I_ + cell) * F_ + k0 + lk];
        As[lk + 0][lm] = av.x; As[lk + 1][lm] = av.y;
        As[lk + 2][lm] = av.z; As[lk + 3][lm] = av.w;
        // B: [16 x 128] tile = 512 float4, 2 per thread
#pragma unroll
        for (int s = 0; s < 2; s++) {
            int idx = t + 256 * s;
            int kl = idx >> 5, c4 = idx & 31;
            *(float4*)&Bs[kl][c4 * 4] =
                *(const float4*)&Wx[(koff + k0 + kl) * FIVEH + n0 + c4 * 4];
        }
        __syncthreads();
#pragma unroll
        for (int k = 0; k < 16; k++) {
            float4 a4 = *(const float4*)&As[k][ty * 4];
            float4 b0 = *(const float4*)&Bs[k][tx * 8];
            float4 b1 = *(const float4*)&Bs[k][tx * 8 + 4];
            float a[4]  = {a4.x, a4.y, a4.z, a4.w};
            float bb[8] = {b0.x, b0.y, b0.z, b0.w, b1.x, b1.y, b1.z, b1.w};
#pragma unroll
            for (int r = 0; r < 4; r++)
#pragma unroll
                for (int q = 0; q < 8; q++) acc[r][q] += a[r] * bb[q];
        }
        __syncthreads();
    }

#pragma unroll
    for (int r = 0; r < 4; r++) {
        int m = ty * 4 + r;
        float* dst = &P[(cell * B_ + m) * FIVEH + n0 + tx * 8];
        *(float4*)dst       = make_float4(acc[r][0], acc[r][1], acc[r][2], acc[r][3]);
        *(float4*)(dst + 4) = make_float4(acc[r][4], acc[r][5], acc[r][6], acc[r][7]);
    }
}

// ---------------------------------------------------------------------------
// Diagonal kernel: for each valid cell i on diagonal d (j = d - i), compute
//   pre = PX[i] + PY[j] + bias + [s_hor, s_ver] @ Ws        (K=512, N=1280)
// then the 2D-LSTM gate math, writing S/C (parity d&1) and the output tile.
// CTA: one cell x one h-tile of 64 (covering all 5 gates = 320 columns), so
// each thread's 4x(5x4) register tile holds all 5 gate values for its h's.
// ---------------------------------------------------------------------------
__global__ __launch_bounds__(256) void diag_kernel(
    const float* __restrict__ Ws, const float* __restrict__ bias,
    float* __restrict__ out, int d)
{
    const int i_lo = (d - (O_ - 1) > 0) ? d - (O_ - 1) : 0;
    const int i = i_lo + blockIdx.x;
    const int j = d - i;
    const int h0 = blockIdx.y * 64;

    const int cur = d & 1, prv = cur ^ 1;
    const float* __restrict__ Sp = g_S[prv];
    const float* __restrict__ Cp = g_C[prv];
    float* __restrict__ Sc = g_S[cur];
    float* __restrict__ Cc = g_C[cur];

    __shared__ float As[16][68];
    __shared__ float Bs[16][320];

    const int t  = threadIdx.x;
    const int tx = t & 15, ty = t >> 4;
    const int lm = t >> 2, lk = (t & 3) * 4;

    const bool has_hor = (i > 0);
    const bool has_ver = (j > 0);
    const float* ShorB = Sp + (size_t)(i - 1) * B_ * H_;
    const float* SverB = Sp + (size_t)i * B_ * H_;

    float acc[4][5][4];
#pragma unroll
    for (int r = 0; r < 4; r++)
#pragma unroll
        for (int g = 0; g < 5; g++)
#pragma unroll
            for (int q = 0; q < 4; q++) acc[r][g][q] = 0.f;

    for (int kt = 0; kt < 32; kt++) {
        const int k0 = kt * 16;
        // A tile: s_hor for k<256, s_ver for k>=256, masked to zero at edges
        float4 av = make_float4(0.f, 0.f, 0.f, 0.f);
        if (k0 < 256) {
            if (has_hor) av = *(const float4*)&ShorB[lm * H_ + k0 + lk];
        } else {
            if (has_ver) av = *(const float4*)&SverB[lm * H_ + (k0 - 256) + lk];
        }
        As[lk + 0][lm] = av.x; As[lk + 1][lm] = av.y;
        As[lk + 2][lm] = av.z; As[lk + 3][lm] = av.w;
        // B tile: 16 x 320 (5 gates x 64 h) = 1280 float4, 5 per thread
#pragma unroll
        for (int s = 0; s < 5; s++) {
            int idx = t + 256 * s;        // 0..1279
            int kl = idx / 80;            // 0..15
            int nl = (idx % 80) * 4;      // 0..316
            int g = nl >> 6;              // gate
            int hh = nl & 63;
            *(float4*)&Bs[kl][nl] =
                *(const float4*)&Ws[(k0 + kl) * FIVEH + g * H_ + h0 + hh];
        }
        __syncthreads();
#pragma unroll
        for (int k = 0; k < 16; k++) {
            float4 a4 = *(const float4*)&As[k][ty * 4];
            float a[4] = {a4.x, a4.y, a4.z, a4.w};
#pragma unroll
            for (int g = 0; g < 5; g++) {
                float4 b = *(const float4*)&Bs[k][g * 64 + tx * 4];
#pragma unroll
                for (int r = 0; r < 4; r++) {
                    acc[r][g][0] += a[r] * b.x;
                    acc[r][g][1] += a[r] * b.y;
                    acc[r][g][2] += a[r] * b.z;
                    acc[r][g][3] += a[r] * b.w;
                }
            }
        }
        __syncthreads();
    }

    // ---------------- epilogue: gates + state update + output ----------------
    const float* PXr = g_PX + (size_t)i * B_ * FIVEH;
    const float* PYr = g_PY + (size_t)j * B_ * FIVEH;
    const int hbase = h0 + tx * 4;

#pragma unroll
    for (int r = 0; r < 4; r++) {
        const int m = ty * 4 + r;   // batch index
        float pre[5][4];
#pragma unroll
        for (int g = 0; g < 5; g++) {
            const int col = g * H_ + hbase;
            float4 px = *(const float4*)&PXr[m * FIVEH + col];
            float4 py = *(const float4*)&PYr[m * FIVEH + col];
            float4 bb = *(const float4*)&bias[col];
            pre[g][0] = acc[r][g][0] + px.x + py.x + bb.x;
            pre[g][1] = acc[r][g][1] + px.y + py.y + bb.y;
            pre[g][2] = acc[r][g][2] + px.z + py.z + bb.z;
            pre[g][3] = acc[r][g][3] + px.w + py.w + bb.w;
        }

        float4 ch4 = make_float4(0.f, 0.f, 0.f, 0.f);
        float4 cv4 = make_float4(0.f, 0.f, 0.f, 0.f);
        if (has_hor) ch4 = *(const float4*)&Cp[((i - 1) * B_ + m) * H_ + hbase];
        if (has_ver) cv4 = *(const float4*)&Cp[(i * B_ + m) * H_ + hbase];
        float ch[4] = {ch4.x, ch4.y, ch4.z, ch4.w};
        float cv[4] = {cv4.x, cv4.y, cv4.z, cv4.w};

        float so[4], co[4];
#pragma unroll
        for (int q = 0; q < 4; q++) {
            float ig = sigf(pre[0][q]);
            float fg = sigf(pre[1][q]);
            float og = sigf(pre[2][q]);
            float lg = sigf(pre[3][q]);
            float gg = tanhf(pre[4][q]);
            float c = fg * (lg * ch[q] + (1.f - lg) * cv[q]) + ig * gg;
            float s = og * tanhf(c);
            co[q] = c; so[q] = s;
        }
        *(float4*)&Sc[(i * B_ + m) * H_ + hbase] = make_float4(so[0], so[1], so[2], so[3]);
        *(float4*)&Cc[(i * B_ + m) * H_ + hbase] = make_float4(co[0], co[1], co[2], co[3]);
        *(float4*)&out[(((size_t)i * O_ + j) * B_ + m) * H_ + hbase] =
            make_float4(so[0], so[1], so[2], so[3]);
    }
}

// ---------------------------------------------------------------------------
extern "C" void kernel_launch(void* const* d_in, const int* in_sizes, int n_in,
                              void* d_out, int out_size)
{
    const float* x  = (const float*)d_in[0];   // (B, I, F)
    const float* y  = (const float*)d_in[1];   // (B, O, F)
    const float* Wx = (const float*)d_in[2];   // (2F, 5H)
    const float* Ws = (const float*)d_in[3];   // (2H, 5H)
    const float* b  = (const float*)d_in[4];   // (5H,)
    float* out = (float*)d_out;                // (I, O, B, H)

    // Hoisted input projection: PX = x@Wx_top, PY = y@Wx_bot
    precompute_kernel<<<dim3(I_, FIVEH / 128, 2), 256>>>(x, y, Wx);

    // Wavefront over 95 anti-diagonals (sequential dependency)
    for (int d = 0; d < I_ + O_ - 1; d++) {
        int i_lo = (d - (O_ - 1) > 0) ? d - (O_ - 1) : 0;
        int i_hi = (d < I_ - 1) ? d : I_ - 1;
        int nv = i_hi - i_lo + 1;
        diag_kernel<<<dim3(nv, 4), 256>>>(Ws, b, out, d);
    }
}

// round 2
// speedup vs baseline: 1.4390x; 1.4390x over previous
#include <cuda_runtime.h>
#include <math.h>

#define B_    64
#define I_    48
#define O_    48
#define F_    256
#define H_    256
#define FIVEH 1280

// ---------------- scratch (device globals; no allocations allowed) ----------
__device__ float g_PX[I_ * B_ * FIVEH];      // x @ Wx[:F]      per (i,b,col)
__device__ float g_PY[O_ * B_ * FIVEH];      // y @ Wx[F:2F]    per (j,b,col)
__device__ float g_S[2][I_ * B_ * H_];       // double-buffered s state
__device__ float g_C[2][I_ * B_ * H_];       // double-buffered c state

__device__ __forceinline__ float sigf(float x) { return 1.0f / (1.0f + expf(-x)); }

// -------- packed fp32x2 helpers (Blackwell dual fp32 FMA; exact IEEE fp32) --
__device__ __forceinline__ unsigned long long pack2(float lo, float hi) {
    unsigned long long r;
    asm("mov.b64 %0, {%1, %2};" : "=l"(r) : "f"(lo), "f"(hi));
    return r;
}
__device__ __forceinline__ void unpack2(unsigned long long v, float& lo, float& hi) {
    asm("mov.b64 {%0, %1}, %2;" : "=f"(lo), "=f"(hi) : "l"(v));
}
__device__ __forceinline__ void fma2(unsigned long long& acc,
                                     unsigned long long a, unsigned long long b) {
    asm("fma.rn.f32x2 %0, %1, %2, %0;" : "+l"(acc) : "l"(a), "l"(b));
}

// ---------------------------------------------------------------------------
// Precompute kernel (unchanged from R1; ~1.5% of runtime).
// P[cell][b][col] = sum_k A[b][cell][k] * Wx[k + koff][col]
// ---------------------------------------------------------------------------
__global__ __launch_bounds__(256) void precompute_kernel(
    const float* __restrict__ x, const float* __restrict__ y,
    const float* __restrict__ Wx)
{
    const int cell  = blockIdx.x;
    const int n0    = blockIdx.y * 128;
    const int which = blockIdx.z;

    const float* A    = which ? y : x;
    const int    koff = which ? F_ : 0;
    float*       P    = which ? g_PY : g_PX;

    __shared__ float As[16][68];
    __shared__ float Bs[16][128];

    const int t  = threadIdx.x;
    const int tx = t & 15, ty = t >> 4;
    const int lm = t >> 2, lk = (t & 3) * 4;

    float acc[4][8];
#pragma unroll
    for (int r = 0; r < 4; r++)
#pragma unroll
        for (int q = 0; q < 8; q++) acc[r][q] = 0.f;

    for (int k0 = 0; k0 < F_; k0 += 16) {
        float4 av = *(const float4*)&A[(lm * I_ + cell) * F_ + k0 + lk];
        As[lk + 0][lm] = av.x; As[lk + 1][lm] = av.y;
        As[lk + 2][lm] = av.z; As[lk + 3][lm] = av.w;
#pragma unroll
        for (int s = 0; s < 2; s++) {
            int idx = t + 256 * s;
            int kl = idx >> 5, c4 = idx & 31;
            *(float4*)&Bs[kl][c4 * 4] =
                *(const float4*)&Wx[(koff + k0 + kl) * FIVEH + n0 + c4 * 4];
        }
        __syncthreads();
#pragma unroll
        for (int k = 0; k < 16; k++) {
            float4 a4 = *(const float4*)&As[k][ty * 4];
            float4 b0 = *(const float4*)&Bs[k][tx * 8];
            float4 b1 = *(const float4*)&Bs[k][tx * 8 + 4];
            float a[4]  = {a4.x, a4.y, a4.z, a4.w};
            float bb[8] = {b0.x, b0.y, b0.z, b0.w, b1.x, b1.y, b1.z, b1.w};
#pragma unroll
            for (int r = 0; r < 4; r++)
#pragma unroll
                for (int q = 0; q < 8; q++) acc[r][q] += a[r] * bb[q];
        }
        __syncthreads();
    }

#pragma unroll
    for (int r = 0; r < 4; r++) {
        int m = ty * 4 + r;
        float* dst = &P[(cell * B_ + m) * FIVEH + n0 + tx * 8];
        *(float4*)dst       = make_float4(acc[r][0], acc[r][1], acc[r][2], acc[r][3]);
        *(float4*)(dst + 4) = make_float4(acc[r][4], acc[r][5], acc[r][6], acc[r][7]);
    }
}

// ---------------------------------------------------------------------------
// Diagonal kernel (R2): N-tile = 32 h x 5 gates = 160 cols, 8 h-tiles.
// Inner product runs on packed fp32x2 (pairs along h). Per thread:
// 4 batches x 5 gates x 1 h-pair = 20 f32x2 accumulators.
// ---------------------------------------------------------------------------
__global__ __launch_bounds__(256, 2) void diag_kernel(
    const float* __restrict__ Ws, const float* __restrict__ bias,
    float* __restrict__ out, int d)
{
    const int i_lo = (d - (O_ - 1) > 0) ? d - (O_ - 1) : 0;
    const int i = i_lo + blockIdx.x;
    const int j = d - i;
    const int h0 = blockIdx.y * 32;

    const int cur = d & 1, prv = cur ^ 1;
    const float* __restrict__ Sp = g_S[prv];
    const float* __restrict__ Cp = g_C[prv];
    float* __restrict__ Sc = g_S[cur];
    float* __restrict__ Cc = g_C[cur];

    __shared__ float As[16][68];
    __shared__ float Bs[16][160];

    const int t  = threadIdx.x;
    const int tx = t & 15, ty = t >> 4;   // tx: h-pair (16x2=32 h), ty: batch/4
    const int lm = t >> 2, lk = (t & 3) * 4;

    const bool has_hor = (i > 0);
    const bool has_ver = (j > 0);
    const float* ShorB = Sp + (size_t)(i - 1) * B_ * H_;
    const float* SverB = Sp + (size_t)i * B_ * H_;

    unsigned long long acc[4][5];
#pragma unroll
    for (int r = 0; r < 4; r++)
#pragma unroll
        for (int g = 0; g < 5; g++) acc[r][g] = 0ull;

    for (int kt = 0; kt < 32; kt++) {
        const int k0 = kt * 16;
        // A tile: s_hor for k<256, s_ver for k>=256, masked to zero at edges
        float4 av = make_float4(0.f, 0.f, 0.f, 0.f);
        if (k0 < 256) {
            if (has_hor) av = *(const float4*)&ShorB[lm * H_ + k0 + lk];
        } else {
            if (has_ver) av = *(const float4*)&SverB[lm * H_ + (k0 - 256) + lk];
        }
        As[lk + 0][lm] = av.x; As[lk + 1][lm] = av.y;
        As[lk + 2][lm] = av.z; As[lk + 3][lm] = av.w;
        // B tile: 16 x 160 (5 gates x 32 h) = 1280 float2, 5 per thread
#pragma unroll
        for (int s = 0; s < 5; s++) {
            int idx = t + 256 * s;        // 0..1279
            int kl = idx / 80;            // 0..15
            int nl = (idx % 80) * 2;      // 0..158
            int g  = nl >> 5;             // gate
            int hh = nl & 31;
            *(float2*)&Bs[kl][nl] =
                *(const float2*)&Ws[(k0 + kl) * FIVEH + g * H_ + h0 + hh];
        }
        __syncthreads();
#pragma unroll
        for (int k = 0; k < 16; k++) {
            float4 a4 = *(const float4*)&As[k][ty * 4];
            unsigned long long a2[4];
            a2[0] = pack2(a4.x, a4.x);
            a2[1] = pack2(a4.y, a4.y);
            a2[2] = pack2(a4.z, a4.z);
            a2[3] = pack2(a4.w, a4.w);
#pragma unroll
            for (int g = 0; g < 5; g++) {
                unsigned long long b2 =
                    *(const unsigned long long*)&Bs[k][g * 32 + tx * 2];
#pragma unroll
                for (int r = 0; r < 4; r++) fma2(acc[r][g], a2[r], b2);
            }
        }
        __syncthreads();
    }

    // ---------------- epilogue: gates + state update + output ----------------
    const float* PXr = g_PX + (size_t)i * B_ * FIVEH;
    const float* PYr = g_PY + (size_t)j * B_ * FIVEH;
    const int hbase = h0 + tx * 2;

    float2 bb[5];
#pragma unroll
    for (int g = 0; g < 5; g++) bb[g] = *(const float2*)&bias[g * H_ + hbase];

#pragma unroll
    for (int r = 0; r < 4; r++) {
        const int m = ty * 4 + r;   // batch index
        float pre[5][2];
#pragma unroll
        for (int g = 0; g < 5; g++) {
            const int col = g * H_ + hbase;
            float2 px = *(const float2*)&PXr[m * FIVEH + col];
            float2 py = *(const float2*)&PYr[m * FIVEH + col];
            float lo, hi; unpack2(acc[r][g], lo, hi);
            pre[g][0] = lo + px.x + py.x + bb[g].x;
            pre[g][1] = hi + px.y + py.y + bb[g].y;
        }

        float2 ch2 = make_float2(0.f, 0.f);
        float2 cv2 = make_float2(0.f, 0.f);
        if (has_hor) ch2 = *(const float2*)&Cp[((i - 1) * B_ + m) * H_ + hbase];
        if (has_ver) cv2 = *(const float2*)&Cp[(i * B_ + m) * H_ + hbase];
        float ch[2] = {ch2.x, ch2.y};
        float cv[2] = {cv2.x, cv2.y};

        float so[2], co[2];
#pragma unroll
        for (int q = 0; q < 2; q++) {
            float ig = sigf(pre[0][q]);
            float fg = sigf(pre[1][q]);
            float og = sigf(pre[2][q]);
            float lg = sigf(pre[3][q]);
            float gg = tanhf(pre[4][q]);
            float c = fg * (lg * ch[q] + (1.f - lg) * cv[q]) + ig * gg;
            float s = og * tanhf(c);
            co[q] = c; so[q] = s;
        }
        *(float2*)&Sc[(i * B_ + m) * H_ + hbase] = make_float2(so[0], so[1]);
        *(float2*)&Cc[(i * B_ + m) * H_ + hbase] = make_float2(co[0], co[1]);
        *(float2*)&out[(((size_t)i * O_ + j) * B_ + m) * H_ + hbase] =
            make_float2(so[0], so[1]);
    }
}

// ---------------------------------------------------------------------------
extern "C" void kernel_launch(void* const* d_in, const int* in_sizes, int n_in,
                              void* d_out, int out_size)
{
    const float* x  = (const float*)d_in[0];   // (B, I, F)
    const float* y  = (const float*)d_in[1];   // (B, O, F)
    const float* Wx = (const float*)d_in[2];   // (2F, 5H)
    const float* Ws = (const float*)d_in[3];   // (2H, 5H)
    const float* b  = (const float*)d_in[4];   // (5H,)
    float* out = (float*)d_out;                // (I, O, B, H)

    // Hoisted input projection: PX = x@Wx_top, PY = y@Wx_bot
    precompute_kernel<<<dim3(I_, FIVEH / 128, 2), 256>>>(x, y, Wx);

    // Wavefront over 95 anti-diagonals (sequential dependency)
    for (int d = 0; d < I_ + O_ - 1; d++) {
        int i_lo = (d - (O_ - 1) > 0) ? d - (O_ - 1) : 0;
        int i_hi = (d < I_ - 1) ? d : I_ - 1;
        int nv = i_hi - i_lo + 1;
        diag_kernel<<<dim3(nv, 8), 256>>>(Ws, b, out, d);
    }
}

// round 4
// speedup vs baseline: 2.1677x; 1.5063x over previous
#include <cuda_runtime.h>
#include <cuda_bf16.h>
#include <stdint.h>
#include <math.h>

#define B_    64
#define I_    48
#define O_    48
#define F_    256
#define H_    256
#define FIVEH 1280
#define KST   512
#define PRE_ROWS 3072            // 24 mtiles * 128
#define STAGE 55296              // A: 128*144(B) + B: 256*144(B)
#define ASIZE 18432
#define SMEM_TOTAL (2 * STAGE)   // 110592

// ---------------- scratch (device globals) ----------------------------------
__device__ float g_PX[I_ * B_ * FIVEH];
__device__ float g_PY[O_ * B_ * FIVEH];
__device__ __nv_bfloat16 g_WT_hi[FIVEH * KST];   // Ws^T [n][k], bf16 hi
__device__ __nv_bfloat16 g_WT_lo[FIVEH * KST];   // residual
__device__ __nv_bfloat16 g_Shi[2][I_ * B_ * H_];
__device__ __nv_bfloat16 g_Slo[2][I_ * B_ * H_];
__device__ float g_C[2][I_ * B_ * H_];
__device__ float g_PRE[3][PRE_ROWS * FIVEH];     // split-K partial pre-activations

__device__ __forceinline__ float sigf(float x) { return 1.0f / (1.0f + expf(-x)); }

__device__ __forceinline__ uint32_t smem_u32(const void* p) {
    uint32_t a;
    asm("{ .reg .u64 t; cvta.to.shared.u64 t, %1; cvt.u32.u64 %0, t; }" : "=r"(a) : "l"(p));
    return a;
}
__device__ __forceinline__ void cp16(uint32_t dst, const void* src, bool v) {
    int sz = v ? 16 : 0;
    asm volatile("cp.async.cg.shared.global [%0], [%1], 16, %2;"
                 :: "r"(dst), "l"(src), "r"(sz) : "memory");
}
#define CP_COMMIT() asm volatile("cp.async.commit_group;" ::: "memory")
#define CP_WAIT(n)  asm volatile("cp.async.wait_group %0;" :: "n"(n) : "memory")

__device__ __forceinline__ void ldmA(uint32_t* a, uint32_t addr) {
    asm volatile("ldmatrix.sync.aligned.m8n8.x4.shared.b16 {%0,%1,%2,%3}, [%4];"
                 : "=r"(a[0]), "=r"(a[1]), "=r"(a[2]), "=r"(a[3]) : "r"(addr));
}
__device__ __forceinline__ void ldmB(uint32_t* b, uint32_t addr) {
    asm volatile("ldmatrix.sync.aligned.m8n8.x2.shared.b16 {%0,%1}, [%2];"
                 : "=r"(b[0]), "=r"(b[1]) : "r"(addr));
}
__device__ __forceinline__ void mma16816(float* c, const uint32_t* a, const uint32_t* b) {
    asm volatile("mma.sync.aligned.m16n8k16.row.col.f32.bf16.bf16.f32 "
                 "{%0,%1,%2,%3}, {%4,%5,%6,%7}, {%8,%9}, {%0,%1,%2,%3};"
                 : "+f"(c[0]), "+f"(c[1]), "+f"(c[2]), "+f"(c[3])
                 : "r"(a[0]), "r"(a[1]), "r"(a[2]), "r"(a[3]), "r"(b[0]), "r"(b[1]));
}

// ---------------------------------------------------------------------------
// Setup: split + transpose Ws into bf16 hi/lo, [n][k]
// ---------------------------------------------------------------------------
__global__ __launch_bounds__(256) void split_ws_kernel(const float* __restrict__ Ws) {
    int idx = blockIdx.x * 256 + threadIdx.x;
    if (idx >= FIVEH * KST) return;
    int n = idx / KST, k = idx % KST;
    float w = Ws[k * FIVEH + n];
    __nv_bfloat16 hi = __float2bfloat16(w);
    g_WT_hi[idx] = hi;
    g_WT_lo[idx] = __float2bfloat16(w - __bfloat162float(hi));
}

// ---------------------------------------------------------------------------
// Precompute: PX = x@Wx_top, PY = y@Wx_bot (fp32 SIMT; ~1.5% of runtime)
// ---------------------------------------------------------------------------
__global__ __launch_bounds__(256) void precompute_kernel(
    const float* __restrict__ x, const float* __restrict__ y,
    const float* __restrict__ Wx)
{
    const int cell = blockIdx.x, n0 = blockIdx.y * 128, which = blockIdx.z;
    const float* A = which ? y : x;
    const int koff = which ? F_ : 0;
    float* P = which ? g_PY : g_PX;

    __shared__ float As[16][68];
    __shared__ float Bs[16][128];
    const int t = threadIdx.x;
    const int tx = t & 15, ty = t >> 4;
    const int lm = t >> 2, lk = (t & 3) * 4;

    float acc[4][8];
#pragma unroll
    for (int r = 0; r < 4; r++)
#pragma unroll
        for (int q = 0; q < 8; q++) acc[r][q] = 0.f;

    for (int k0 = 0; k0 < F_; k0 += 16) {
        float4 av = *(const float4*)&A[(lm * I_ + cell) * F_ + k0 + lk];
        As[lk + 0][lm] = av.x; As[lk + 1][lm] = av.y;
        As[lk + 2][lm] = av.z; As[lk + 3][lm] = av.w;
#pragma unroll
        for (int s = 0; s < 2; s++) {
            int idx = t + 256 * s;
            int kl = idx >> 5, c4 = idx & 31;
            *(float4*)&Bs[kl][c4 * 4] =
                *(const float4*)&Wx[(koff + k0 + kl) * FIVEH + n0 + c4 * 4];
        }
        __syncthreads();
#pragma unroll
        for (int k = 0; k < 16; k++) {
            float4 a4 = *(const float4*)&As[k][ty * 4];
            float4 b0 = *(const float4*)&Bs[k][tx * 8];
            float4 b1 = *(const float4*)&Bs[k][tx * 8 + 4];
            float a[4] = {a4.x, a4.y, a4.z, a4.w};
            float bb[8] = {b0.x, b0.y, b0.z, b0.w, b1.x, b1.y, b1.z, b1.w};
#pragma unroll
            for (int r = 0; r < 4; r++)
#pragma unroll
                for (int q = 0; q < 8; q++) acc[r][q] += a[r] * bb[q];
        }
        __syncthreads();
    }
#pragma unroll
    for (int r = 0; r < 4; r++) {
        int m = ty * 4 + r;
        float* dst = &P[(cell * B_ + m) * FIVEH + n0 + tx * 8];
        *(float4*)dst       = make_float4(acc[r][0], acc[r][1], acc[r][2], acc[r][3]);
        *(float4*)(dst + 4) = make_float4(acc[r][4], acc[r][5], acc[r][6], acc[r][7]);
    }
}

// ---------------------------------------------------------------------------
// GEMM: pre[term][pos][n] = s-states @ Ws_term, M-tile 128, N-tile 256, K=512
// grid = (ceil(nv/2), 5, 3). HMMA m16n8k16 bf16, 8 warps, warp tile 64x64.
// ---------------------------------------------------------------------------
__global__ __launch_bounds__(256, 1) void gemm_kernel(int d)
{
    extern __shared__ char smem[];
    const uint32_t sb = smem_u32(smem);
    const int t = threadIdx.x;
    const int i_lo = (d > O_ - 1) ? d - (O_ - 1) : 0;
    const int i_hi = (d < I_ - 1) ? d : I_ - 1;
    const int i0 = i_lo + 2 * (int)blockIdx.x;
    const int ny = blockIdx.y;
    const int term = blockIdx.z;
    const int prv = (d & 1) ^ 1;

    const __nv_bfloat16* __restrict__ Ssrc = (term == 1) ? g_Slo[prv] : g_Shi[prv];
    const __nv_bfloat16* __restrict__ Wsrc = (term == 2) ? g_WT_lo : g_WT_hi;

    // ---- chunk loader: k-chunk c8 (64 wide) into stage buf ----
    auto load_chunk = [&](int c8, int buf) {
        const bool hor = (c8 < 4);
        const int kc = (c8 & 3) * 64;
        const int kr = c8 * 64;
        const uint32_t base = sb + buf * STAGE;
#pragma unroll
        for (int p = 0; p < 4; p++) {                 // A: 128 rows x 64 k
            int idx = t + 256 * p;
            int row = idx >> 3, seg = idx & 7;
            int cell = i0 + (row >> 6);
            int b = row & 63;
            bool cv = (cell <= i_hi);
            bool valid; int scell;
            if (hor) { valid = cv && (cell > 0); scell = cell - 1; }
            else     { valid = cv && (d - cell > 0); scell = cell; }
            const __nv_bfloat16* g = valid ?
                (Ssrc + ((scell * B_) + b) * H_ + kc + seg * 8) : Ssrc;
            cp16(base + row * 144 + seg * 16, g, valid);
        }
#pragma unroll
        for (int p = 0; p < 8; p++) {                 // B: 256 n-rows x 64 k
            int idx = t + 256 * p;
            int rr = idx >> 3, seg = idx & 7;
            const __nv_bfloat16* g = Wsrc + (ny * 256 + rr) * KST + kr + seg * 8;
            cp16(base + ASIZE + rr * 144 + seg * 16, g, true);
        }
    };

    const int wid = t >> 5, lane = t & 31;
    const int wm = wid >> 2, wn = wid & 3;            // 2 x 4 warp grid
    const int m0 = wm * 64, n0 = wn * 64;

    // lane-invariant parts of ldmatrix addresses
    const uint32_t aoff = (uint32_t)((m0 + ((lane >> 3) & 1) * 8 + (lane & 7)) * 144
                                     + (lane >> 4) * 16);
    const uint32_t boff = (uint32_t)(ASIZE + (n0 + (lane & 7)) * 144
                                     + ((lane >> 3) & 1) * 16);

    float acc[4][8][4];
#pragma unroll
    for (int f = 0; f < 4; f++)
#pragma unroll
        for (int e = 0; e < 8; e++)
#pragma unroll
            for (int q = 0; q < 4; q++) acc[f][e][q] = 0.f;

    load_chunk(0, 0);
    CP_COMMIT();

    for (int c8 = 0; c8 < 8; c8++) {
        if (c8 < 7) {
            load_chunk(c8 + 1, (c8 + 1) & 1);
            CP_COMMIT();
            CP_WAIT(1);
        } else {
            CP_WAIT(0);
        }
        __syncthreads();

        const uint32_t bufb = sb + (c8 & 1) * STAGE;
#pragma unroll
        for (int ks = 0; ks < 4; ks++) {
            uint32_t afr[4][4];
#pragma unroll
            for (int f = 0; f < 4; f++)
                ldmA(afr[f], bufb + aoff + f * 2304 + ks * 32);
            uint32_t bfr[8][2];
#pragma unroll
            for (int e = 0; e < 8; e++)
                ldmB(bfr[e], bufb + boff + e * 1152 + ks * 32);
#pragma unroll
            for (int f = 0; f < 4; f++)
#pragma unroll
                for (int e = 0; e < 8; e++)
                    mma16816(acc[f][e], afr[f], bfr[e]);
        }
        if (c8 < 7) __syncthreads();
    }

    // ---- store pre (fp32) ----
    float* __restrict__ PRE = g_PRE[term];
    const int rbase = (int)blockIdx.x * 128 + m0 + (lane >> 2);
    const int cbase = ny * 256 + n0 + (lane & 3) * 2;
#pragma unroll
    for (int f = 0; f < 4; f++) {
#pragma unroll
        for (int e = 0; e < 8; e++) {
            const int r0 = rbase + 16 * f;
            const int cc = cbase + 8 * e;
            *(float2*)&PRE[(size_t)r0 * FIVEH + cc]       = make_float2(acc[f][e][0], acc[f][e][1]);
            *(float2*)&PRE[(size_t)(r0 + 8) * FIVEH + cc] = make_float2(acc[f][e][2], acc[f][e][3]);
        }
    }
}

// ---------------------------------------------------------------------------
// Pointwise: sum 3 pre terms + PX + PY + bias, gate math, write states + out
// grid = (nv, 8), block 256 (threads map h)
// ---------------------------------------------------------------------------
__global__ __launch_bounds__(256) void point_kernel(
    const float* __restrict__ bias, float* __restrict__ out, int d)
{
    const int i_lo = (d > O_ - 1) ? d - (O_ - 1) : 0;
    const int q = blockIdx.x;
    const int i = i_lo + q;
    const int j = d - i;
    const int h = threadIdx.x;
    const int cur = d & 1, prv = cur ^ 1;
    const bool hh = (i > 0), vv = (j > 0);

    const float* __restrict__ Cp = g_C[prv];
    float* __restrict__ Cc = g_C[cur];
    __nv_bfloat16* __restrict__ Shc = g_Shi[cur];
    __nv_bfloat16* __restrict__ Slc = g_Slo[cur];

    float bb[5];
#pragma unroll
    for (int g = 0; g < 5; g++) bb[g] = bias[g * H_ + h];

#pragma unroll 1
    for (int p = 0; p < 8; p++) {
        const int b = blockIdx.y * 8 + p;
        const size_t pos = (size_t)(q * 64 + b) * FIVEH;
        const size_t pxo = ((size_t)i * B_ + b) * FIVEH;
        const size_t pyo = ((size_t)j * B_ + b) * FIVEH;

        float pre[5];
#pragma unroll
        for (int g = 0; g < 5; g++) {
            const int col = g * H_ + h;
            pre[g] = g_PRE[0][pos + col] + g_PRE[1][pos + col] + g_PRE[2][pos + col]
                   + g_PX[pxo + col] + g_PY[pyo + col] + bb[g];
        }
        float ch = hh ? Cp[(((i - 1) * B_) + b) * H_ + h] : 0.f;
        float cv = vv ? Cp[((i * B_) + b) * H_ + h] : 0.f;

        float ig = sigf(pre[0]);
        float fg = sigf(pre[1]);
        float og = sigf(pre[2]);
        float lg = sigf(pre[3]);
        float gg = tanhf(pre[4]);
        float c = fg * (lg * ch + (1.f - lg) * cv) + ig * gg;
        float s = og * tanhf(c);

        const size_t sidx = ((size_t)i * B_ + b) * H_ + h;
        Cc[sidx] = c;
        __nv_bfloat16 shi = __float2bfloat16(s);
        Shc[sidx] = shi;
        Slc[sidx] = __float2bfloat16(s - __bfloat162float(shi));
        out[(((size_t)i * O_ + j) * B_ + b) * H_ + h] = s;
    }
}

// ---------------------------------------------------------------------------
extern "C" void kernel_launch(void* const* d_in, const int* in_sizes, int n_in,
                              void* d_out, int out_size)
{
    const float* x  = (const float*)d_in[0];
    const float* y  = (const float*)d_in[1];
    const float* Wx = (const float*)d_in[2];
    const float* Ws = (const float*)d_in[3];
    const float* b  = (const float*)d_in[4];
    float* out = (float*)d_out;

    cudaFuncSetAttribute(gemm_kernel, cudaFuncAttributeMaxDynamicSharedMemorySize,
                         SMEM_TOTAL);

    split_ws_kernel<<<(FIVEH * KST + 255) / 256, 256>>>(Ws);
    precompute_kernel<<<dim3(I_, FIVEH / 128, 2), 256>>>(x, y, Wx);

    for (int d = 0; d < I_ + O_ - 1; d++) {
        int i_lo = (d > O_ - 1) ? d - (O_ - 1) : 0;
        int i_hi = (d < I_ - 1) ? d : I_ - 1;
        int nv = i_hi - i_lo + 1;
        int mt = (nv + 1) / 2;
        gemm_kernel<<<dim3(mt, 5, 3), 256, SMEM_TOTAL>>>(d);
        point_kernel<<<dim3(nv, 8), 256>>>(b, out, d);
    }
}